// round 8
// baseline (speedup 1.0000x reference)
#include <cuda_runtime.h>
#include <cuda_fp16.h>
#include <cstdint>
#include <cstddef>

#define NT 512
#define XP 72   // halves per smem matrix row (144B: conflict-free ldmatrix, 16B-aligned)

namespace {
constexpr int Bb = 2, Ss = 512, Ll = 384, CMc = 64;

struct __align__(16) SMem {
    __half x[512 * XP];     // post-LN x fp16, row-major [s][c]      73,728B
    __half vt[512 * XP];    // v, then t                              73,728B
    __half wvg[128 * XP];   // B rows n: n<64 -> wv col n, else wg col n-64; cols k
    __half wot[64 * XP];    // B rows n: wo col n
    float LG[8 * 512];      // logits -> attn [h][s]
    float maskS[512];
    float amt[512];         // a [j][h]
    float pbuf[16 * 64];    // LN-fold qin partials; og partials
    float qin[64];
    float qsm[64];
    float og[64];
    float red[16];
};
}  // namespace

__device__ __forceinline__ uint32_t s2u(const void* p) {
    uint32_t a;
    asm("{ .reg .u64 t; cvta.to.shared.u64 t, %1; cvt.u32.u64 %0, t; }" : "=r"(a) : "l"(p));
    return a;
}
__device__ __forceinline__ void ldmA(uint32_t* a, uint32_t addr) {
    asm volatile("ldmatrix.sync.aligned.m8n8.x4.shared.b16 {%0,%1,%2,%3}, [%4];"
                 : "=r"(a[0]), "=r"(a[1]), "=r"(a[2]), "=r"(a[3]) : "r"(addr));
}
__device__ __forceinline__ void mma16816(float* d, const uint32_t* a, const uint32_t* b) {
    asm volatile(
        "mma.sync.aligned.m16n8k16.row.col.f32.f16.f16.f32 "
        "{%0,%1,%2,%3}, {%4,%5,%6,%7}, {%8,%9}, {%0,%1,%2,%3};"
        : "+f"(d[0]), "+f"(d[1]), "+f"(d[2]), "+f"(d[3])
        : "r"(a[0]), "r"(a[1]), "r"(a[2]), "r"(a[3]), "r"(b[0]), "r"(b[1]));
}
#define BAR_A() asm volatile("bar.sync 1, 256;" ::: "memory")
__device__ __forceinline__ float sgm(float x) { return 1.0f / (1.0f + __expf(-x)); }

__global__ void __launch_bounds__(NT, 1)
msa_col_global_attn(const float* __restrict__ m, const float* __restrict__ msa_mask,
                    const float* __restrict__ lnw, const float* __restrict__ lnb,
                    const float* __restrict__ wq, const float* __restrict__ wk,
                    const float* __restrict__ wv, const float* __restrict__ wg,
                    const float* __restrict__ bg, const float* __restrict__ wo,
                    const float* __restrict__ bo, float* __restrict__ out)
{
    extern __shared__ __align__(16) char smraw[];
    SMem& sm = *reinterpret_cast<SMem*>(smraw);
    const int tid = threadIdx.x;
    const int w = tid >> 5, lane = tid & 31;
    const int b = blockIdx.x / Ll, l = blockIdx.x - b * Ll;
    const size_t rowStride = (size_t)Ll * CMc;
    const float* mBase = m + ((size_t)b * Ss * Ll + l) * CMc;
    float* oBase = out + ((size_t)b * Ss * Ll + l) * CMc;

    // ---- Phase 0: mask + weights + LayerNorm with folded masked column-sum ----
    float mk = msa_mask[((size_t)b * Ss + tid) * Ll + l];
    sm.maskS[tid] = mk;
    {
        float ms = mk;
#pragma unroll
        for (int o = 16; o; o >>= 1) ms += __shfl_xor_sync(0xffffffffu, ms, o);
        if (lane == 0) sm.red[w] = ms;
    }
    for (int idx = tid; idx < 8192; idx += NT) {
        int n = idx & 127, k = idx >> 7;
        float v = (n < 64) ? __ldg(&wv[k * 64 + n]) : __ldg(&wg[k * 64 + (n - 64)]);
        sm.wvg[n * XP + k] = __float2half(v);
    }
    for (int idx = tid; idx < 4096; idx += NT) {
        int n = idx & 63, k = idx >> 6;
        sm.wot[n * XP + k] = __float2half(__ldg(&wo[k * 64 + n]));
    }
    {
        const float lwA = lnw[lane], lwB = lnw[lane + 32];
        const float lbA = lnb[lane], lbB = lnb[lane + 32];
        float qA = 0.f, qB = 0.f;  // masked column sums for cols lane, lane+32
#pragma unroll 1
        for (int rb = 0; rb < 4; rb++) {
            float a0[8], a1[8];
#pragma unroll
            for (int r = 0; r < 8; r++) {
                int s = w * 32 + rb * 8 + r;
                const float* mp = mBase + (size_t)s * rowStride;
                a0[r] = mp[lane];
                a1[r] = mp[lane + 32];
            }
#pragma unroll
            for (int r = 0; r < 8; r++) {
                int s = w * 32 + rb * 8 + r;
                float su = a0[r] + a1[r];
                float sq = fmaf(a0[r], a0[r], a1[r] * a1[r]);
#pragma unroll
                for (int o = 16; o; o >>= 1) {
                    su += __shfl_xor_sync(0xffffffffu, su, o);
                    sq += __shfl_xor_sync(0xffffffffu, sq, o);
                }
                float mu = su * (1.0f / 64.0f);
                float var = sq * (1.0f / 64.0f) - mu * mu;
                float rs = rsqrtf(var + 1e-5f);
                float vA = (a0[r] - mu) * rs * lwA + lbA;
                float vB = (a1[r] - mu) * rs * lwB + lbB;
                sm.x[s * XP + lane]      = __float2half(vA);
                sm.x[s * XP + lane + 32] = __float2half(vB);
                float mks = __shfl_sync(0xffffffffu, mk, rb * 8 + r);
                qA = fmaf(vA, mks, qA);
                qB = fmaf(vB, mks, qB);
            }
        }
        sm.pbuf[w * 64 + lane]      = qA;
        sm.pbuf[w * 64 + lane + 32] = qB;
    }
    __syncthreads();  // S1: x, weights, mask, qin partials ready

    if (w < 8) {
        // ================== GROUP A: scalar attention chain ==================
        if (tid < 64) {
            float acc = 0.f;
#pragma unroll
            for (int i = 0; i < 16; i++) acc += sm.pbuf[i * 64 + tid];
            float d = 0.f;
#pragma unroll
            for (int i = 0; i < 16; i++) d += sm.red[i];
            sm.qin[tid] = acc / fmaxf(d, 1.0f);
        }
        BAR_A();
        if (tid < 64) {
            float acc = 0.f;
#pragma unroll
            for (int j = 0; j < 64; j++) acc = fmaf(sm.qin[j], __ldg(&wq[j * 64 + tid]), acc);
            sm.qsm[tid] = acc;
        }
        BAR_A();
        {
#pragma unroll
            for (int t2 = 0; t2 < 2; t2++) {
                int idx = 2 * tid + t2;
                int j = idx >> 3, h = idx & 7;
                float acc = 0.f;
#pragma unroll
                for (int c = 0; c < 8; c++)
                    acc = fmaf(sm.qsm[h * 8 + c], __ldg(&wk[j * 64 + h * 8 + c]), acc);
                sm.amt[j * 8 + h] = acc * 0.35355339059327373f;  // 1/sqrt(C)
            }
        }
        BAR_A();
        // logits: 256 threads x 2 rows
#pragma unroll 1
        for (int rr = 0; rr < 2; rr++) {
            int s = tid + rr * 256;
            uint4 raw[8];
#pragma unroll
            for (int q = 0; q < 8; q++)
                raw[q] = *reinterpret_cast<const uint4*>(&sm.x[s * XP + q * 8]);
            const __half* xr = reinterpret_cast<const __half*>(raw);
            float acc[8] = {0, 0, 0, 0, 0, 0, 0, 0};
#pragma unroll
            for (int j = 0; j < 64; j++) {
                float xv = __half2float(xr[j]);
                const float4* ap = reinterpret_cast<const float4*>(&sm.amt[j * 8]);
                float4 q0 = ap[0], q1 = ap[1];
                acc[0] = fmaf(xv, q0.x, acc[0]); acc[1] = fmaf(xv, q0.y, acc[1]);
                acc[2] = fmaf(xv, q0.z, acc[2]); acc[3] = fmaf(xv, q0.w, acc[3]);
                acc[4] = fmaf(xv, q1.x, acc[4]); acc[5] = fmaf(xv, q1.y, acc[5]);
                acc[6] = fmaf(xv, q1.z, acc[6]); acc[7] = fmaf(xv, q1.w, acc[7]);
            }
            float mkk = sm.maskS[s];
#pragma unroll
            for (int h = 0; h < 8; h++) sm.LG[h * 512 + s] = (mkk != 0.0f) ? acc[h] : -1e9f;
        }
        BAR_A();
        // softmax: warp w owns head w
        {
            float vals[16];
            float lm = -3.4e38f;
#pragma unroll
            for (int k = 0; k < 16; k++) {
                vals[k] = sm.LG[w * 512 + lane + k * 32];
                lm = fmaxf(lm, vals[k]);
            }
#pragma unroll
            for (int o = 16; o; o >>= 1) lm = fmaxf(lm, __shfl_xor_sync(0xffffffffu, lm, o));
            float ls = 0.f;
#pragma unroll
            for (int k = 0; k < 16; k++) {
                vals[k] = __expf(vals[k] - lm);
                ls += vals[k];
            }
#pragma unroll
            for (int o = 16; o; o >>= 1) ls += __shfl_xor_sync(0xffffffffu, ls, o);
            float inv = 1.0f / ls;
#pragma unroll
            for (int k = 0; k < 16; k++) sm.LG[w * 512 + lane + k * 32] = vals[k] * inv;
        }
    } else {
        // ================== GROUP B: Pass V = x @ wv -> vt fp16 ==================
        const int mw = (w - 8) >> 1;        // 128-row tile
        const int nw2 = (w - 8) & 1;        // 32-col half
        uint32_t B[4][4][2];
#pragma unroll
        for (int nt = 0; nt < 4; nt++)
#pragma unroll
            for (int kt = 0; kt < 4; kt++) {
                int row = nw2 * 32 + nt * 8 + (lane >> 2);
                int col = kt * 16 + (lane & 3) * 2;
                B[nt][kt][0] = *reinterpret_cast<const uint32_t*>(&sm.wvg[row * XP + col]);
                B[nt][kt][1] = *reinterpret_cast<const uint32_t*>(&sm.wvg[row * XP + col + 8]);
            }
#pragma unroll 1
        for (int mt = 0; mt < 8; mt++) {
            int s0 = mw * 128 + mt * 16;
            uint32_t A[4][4];
#pragma unroll
            for (int kt = 0; kt < 4; kt++)
                ldmA(A[kt], s2u(&sm.x[(s0 + (lane & 15)) * XP + kt * 16 + ((lane >> 4) << 3)]));
            float acc[4][4];
#pragma unroll
            for (int nt = 0; nt < 4; nt++)
#pragma unroll
                for (int q = 0; q < 4; q++) acc[nt][q] = 0.f;
#pragma unroll
            for (int kt = 0; kt < 4; kt++)
#pragma unroll
                for (int nt = 0; nt < 4; nt++) mma16816(acc[nt], A[kt], B[nt][kt]);
            int r = s0 + (lane >> 2), c = nw2 * 32 + (lane & 3) * 2;
#pragma unroll
            for (int nt = 0; nt < 4; nt++) {
                *reinterpret_cast<__half2*>(&sm.vt[r * XP + c + nt * 8]) =
                    __floats2half2_rn(acc[nt][0], acc[nt][1]);
                *reinterpret_cast<__half2*>(&sm.vt[(r + 8) * XP + c + nt * 8]) =
                    __floats2half2_rn(acc[nt][2], acc[nt][3]);
            }
        }
    }
    __syncthreads();  // S2: attn + v ready

    // ---- og[hc] = sum_s attn[hc>>3][s] * v[s][hc] ----
    {
        int hc = tid & 63, ck = tid >> 6;
        const float* ar = &sm.LG[(hc >> 3) * 512 + ck * 64];
        float acc = 0.f;
#pragma unroll 8
        for (int i = 0; i < 64; i++)
            acc = fmaf(ar[i], __half2float(sm.vt[(ck * 64 + i) * XP + hc]), acc);
        sm.pbuf[ck * 64 + hc] = acc;
    }
    __syncthreads();  // S3
    if (tid < 64) {
        float acc = 0.f;
#pragma unroll
        for (int ck = 0; ck < 8; ck++) acc += sm.pbuf[ck * 64 + tid];
        sm.og[tid] = acc;
    }
    __syncthreads();  // S4

    const int mw = w >> 2, nw = w & 3;
    // ---- Pass G: t = og * sigmoid(x @ wg + bg) -> vt (overwrite) ----
    {
        uint32_t B[2][4][2];
#pragma unroll
        for (int nt = 0; nt < 2; nt++)
#pragma unroll
            for (int kt = 0; kt < 4; kt++) {
                int row = 64 + nw * 16 + nt * 8 + (lane >> 2);
                int col = kt * 16 + (lane & 3) * 2;
                B[nt][kt][0] = *reinterpret_cast<const uint32_t*>(&sm.wvg[row * XP + col]);
                B[nt][kt][1] = *reinterpret_cast<const uint32_t*>(&sm.wvg[row * XP + col + 8]);
            }
        int cbase = nw * 16 + (lane & 3) * 2;
        float og0[2], og1[2], bg0[2], bg1[2];
#pragma unroll
        for (int nt = 0; nt < 2; nt++) {
            og0[nt] = sm.og[cbase + nt * 8];
            og1[nt] = sm.og[cbase + nt * 8 + 1];
            bg0[nt] = __ldg(&bg[cbase + nt * 8]);
            bg1[nt] = __ldg(&bg[cbase + nt * 8 + 1]);
        }
#pragma unroll 1
        for (int mt = 0; mt < 8; mt++) {
            int s0 = mw * 128 + mt * 16;
            uint32_t A[4][4];
#pragma unroll
            for (int kt = 0; kt < 4; kt++)
                ldmA(A[kt], s2u(&sm.x[(s0 + (lane & 15)) * XP + kt * 16 + ((lane >> 4) << 3)]));
            float acc[2][4] = {{0, 0, 0, 0}, {0, 0, 0, 0}};
#pragma unroll
            for (int kt = 0; kt < 4; kt++)
#pragma unroll
                for (int nt = 0; nt < 2; nt++) mma16816(acc[nt], A[kt], B[nt][kt]);
            int r = s0 + (lane >> 2);
#pragma unroll
            for (int nt = 0; nt < 2; nt++) {
                float t0 = og0[nt] * sgm(acc[nt][0] + bg0[nt]);
                float t1 = og1[nt] * sgm(acc[nt][1] + bg1[nt]);
                float t2 = og0[nt] * sgm(acc[nt][2] + bg0[nt]);
                float t3 = og1[nt] * sgm(acc[nt][3] + bg1[nt]);
                *reinterpret_cast<__half2*>(&sm.vt[r * XP + cbase + nt * 8]) =
                    __floats2half2_rn(t0, t1);
                *reinterpret_cast<__half2*>(&sm.vt[(r + 8) * XP + cbase + nt * 8]) =
                    __floats2half2_rn(t2, t3);
            }
        }
    }
    __syncthreads();  // S5: t ready

    // ---- Pass O: out = (t @ wo + bo) * mask -> global ----
    {
        uint32_t B[2][4][2];
#pragma unroll
        for (int nt = 0; nt < 2; nt++)
#pragma unroll
            for (int kt = 0; kt < 4; kt++) {
                int row = nw * 16 + nt * 8 + (lane >> 2);
                int col = kt * 16 + (lane & 3) * 2;
                B[nt][kt][0] = *reinterpret_cast<const uint32_t*>(&sm.wot[row * XP + col]);
                B[nt][kt][1] = *reinterpret_cast<const uint32_t*>(&sm.wot[row * XP + col + 8]);
            }
        int cbase = nw * 16 + (lane & 3) * 2;
        float bo0[2], bo1[2];
#pragma unroll
        for (int nt = 0; nt < 2; nt++) {
            bo0[nt] = __ldg(&bo[cbase + nt * 8]);
            bo1[nt] = __ldg(&bo[cbase + nt * 8 + 1]);
        }
#pragma unroll 1
        for (int mt = 0; mt < 8; mt++) {
            int s0 = mw * 128 + mt * 16;
            uint32_t A[4][4];
#pragma unroll
            for (int kt = 0; kt < 4; kt++)
                ldmA(A[kt], s2u(&sm.vt[(s0 + (lane & 15)) * XP + kt * 16 + ((lane >> 4) << 3)]));
            float acc[2][4] = {{0, 0, 0, 0}, {0, 0, 0, 0}};
#pragma unroll
            for (int kt = 0; kt < 4; kt++)
#pragma unroll
                for (int nt = 0; nt < 2; nt++) mma16816(acc[nt], A[kt], B[nt][kt]);
            int r = s0 + (lane >> 2);
            float mkA = sm.maskS[r], mkB = sm.maskS[r + 8];
#pragma unroll
            for (int nt = 0; nt < 2; nt++) {
                *reinterpret_cast<float2*>(oBase + (size_t)r * rowStride + cbase + nt * 8) =
                    make_float2((acc[nt][0] + bo0[nt]) * mkA, (acc[nt][1] + bo1[nt]) * mkA);
                *reinterpret_cast<float2*>(oBase + (size_t)(r + 8) * rowStride + cbase + nt * 8) =
                    make_float2((acc[nt][2] + bo0[nt]) * mkB, (acc[nt][3] + bo1[nt]) * mkB);
            }
        }
    }
}

extern "C" void kernel_launch(void* const* d_in, const int* in_sizes, int n_in,
                              void* d_out, int out_size)
{
    (void)in_sizes; (void)n_in; (void)out_size;
    const float* m    = (const float*)d_in[0];
    const float* mask = (const float*)d_in[1];
    const float* lnw  = (const float*)d_in[2];
    const float* lnb  = (const float*)d_in[3];
    const float* wq   = (const float*)d_in[4];
    const float* wk   = (const float*)d_in[5];
    const float* wv   = (const float*)d_in[6];
    const float* wg   = (const float*)d_in[7];
    const float* bg   = (const float*)d_in[8];
    const float* wo   = (const float*)d_in[9];
    const float* bo   = (const float*)d_in[10];
    float* out = (float*)d_out;

    cudaFuncSetAttribute(msa_col_global_attn,
                         cudaFuncAttributeMaxDynamicSharedMemorySize,
                         (int)sizeof(SMem));
    msa_col_global_attn<<<Bb * Ll, NT, sizeof(SMem)>>>(
        m, mask, lnw, lnb, wq, wk, wv, wg, bg, wo, bo, out);
}

// round 9
// speedup vs baseline: 1.6000x; 1.6000x over previous
#include <cuda_runtime.h>
#include <cuda_fp16.h>
#include <cstdint>
#include <cstddef>

#define NT 512
#define XP 72   // halves per smem matrix row (144B: conflict-free ldmatrix, 16B-aligned)

namespace {
constexpr int Bb = 2, Ss = 512, Ll = 384, CMc = 64;

struct __align__(16) SMem {
    __half x[512 * XP];     // post-LN x fp16, row-major [s][c]      73,728B
    __half vt[512 * XP];    // v, then t                              73,728B
    __half wvg[128 * XP];   // B rows n: n<64 -> wv col n, else wg col n-64; cols k
    __half wot[64 * XP];    // B rows n: wo col n
    float LG[8 * 512];      // logits -> attn [h][s]
    float maskS[512];
    float amt[512];         // a [j][h]
    float pbuf[16 * 64];    // LN-fold qin partials; og partials
    float qin[64];
    float qsm[64];
    float og[64];
    float red[16];
};
}  // namespace

__device__ __forceinline__ uint32_t s2u(const void* p) {
    uint32_t a;
    asm("{ .reg .u64 t; cvta.to.shared.u64 t, %1; cvt.u32.u64 %0, t; }" : "=r"(a) : "l"(p));
    return a;
}
__device__ __forceinline__ void ldmA(uint32_t* a, uint32_t addr) {
    asm volatile("ldmatrix.sync.aligned.m8n8.x4.shared.b16 {%0,%1,%2,%3}, [%4];"
                 : "=r"(a[0]), "=r"(a[1]), "=r"(a[2]), "=r"(a[3]) : "r"(addr));
}
__device__ __forceinline__ void mma16816(float* d, const uint32_t* a, const uint32_t* b) {
    asm volatile(
        "mma.sync.aligned.m16n8k16.row.col.f32.f16.f16.f32 "
        "{%0,%1,%2,%3}, {%4,%5,%6,%7}, {%8,%9}, {%0,%1,%2,%3};"
        : "+f"(d[0]), "+f"(d[1]), "+f"(d[2]), "+f"(d[3])
        : "r"(a[0]), "r"(a[1]), "r"(a[2]), "r"(a[3]), "r"(b[0]), "r"(b[1]));
}
__device__ __forceinline__ float sgm(float x) { return 1.0f / (1.0f + __expf(-x)); }

__global__ void __launch_bounds__(NT, 1)
msa_col_global_attn(const float* __restrict__ m, const float* __restrict__ msa_mask,
                    const float* __restrict__ lnw, const float* __restrict__ lnb,
                    const float* __restrict__ wq, const float* __restrict__ wk,
                    const float* __restrict__ wv, const float* __restrict__ wg,
                    const float* __restrict__ bg, const float* __restrict__ wo,
                    const float* __restrict__ bo, float* __restrict__ out)
{
    extern __shared__ __align__(16) char smraw[];
    SMem& sm = *reinterpret_cast<SMem*>(smraw);
    const int tid = threadIdx.x;
    const int w = tid >> 5, lane = tid & 31;
    const int mw = w >> 2, nw = w & 3;   // warp tile coords for GEMM passes
    const int b = blockIdx.x / Ll, l = blockIdx.x - b * Ll;
    const size_t rowStride = (size_t)Ll * CMc;
    const float* mBase = m + ((size_t)b * Ss * Ll + l) * CMc;
    float* oBase = out + ((size_t)b * Ss * Ll + l) * CMc;

    // ---- Phase 0: mask + weights + LayerNorm with folded masked column-sum ----
    float mk = msa_mask[((size_t)b * Ss + tid) * Ll + l];
    sm.maskS[tid] = mk;
    {
        float ms = mk;
#pragma unroll
        for (int o = 16; o; o >>= 1) ms += __shfl_xor_sync(0xffffffffu, ms, o);
        if (lane == 0) sm.red[w] = ms;
    }
    for (int idx = tid; idx < 8192; idx += NT) {
        int n = idx & 127, k = idx >> 7;
        float v = (n < 64) ? __ldg(&wv[k * 64 + n]) : __ldg(&wg[k * 64 + (n - 64)]);
        sm.wvg[n * XP + k] = __float2half(v);
    }
    for (int idx = tid; idx < 4096; idx += NT) {
        int n = idx & 63, k = idx >> 6;
        sm.wot[n * XP + k] = __float2half(__ldg(&wo[k * 64 + n]));
    }
    {
        const float lwA = lnw[lane], lwB = lnw[lane + 32];
        const float lbA = lnb[lane], lbB = lnb[lane + 32];
        float qA = 0.f, qB = 0.f;  // masked column sums for cols lane, lane+32
#pragma unroll 1
        for (int rb = 0; rb < 4; rb++) {
            float a0[8], a1[8];
#pragma unroll
            for (int r = 0; r < 8; r++) {
                int s = w * 32 + rb * 8 + r;
                const float* mp = mBase + (size_t)s * rowStride;
                a0[r] = mp[lane];
                a1[r] = mp[lane + 32];
            }
#pragma unroll
            for (int r = 0; r < 8; r++) {
                int s = w * 32 + rb * 8 + r;
                float su = a0[r] + a1[r];
                float sq = fmaf(a0[r], a0[r], a1[r] * a1[r]);
#pragma unroll
                for (int o = 16; o; o >>= 1) {
                    su += __shfl_xor_sync(0xffffffffu, su, o);
                    sq += __shfl_xor_sync(0xffffffffu, sq, o);
                }
                float mu = su * (1.0f / 64.0f);
                float var = sq * (1.0f / 64.0f) - mu * mu;
                float rs = rsqrtf(var + 1e-5f);
                float vA = (a0[r] - mu) * rs * lwA + lbA;
                float vB = (a1[r] - mu) * rs * lwB + lbB;
                sm.x[s * XP + lane]      = __float2half(vA);
                sm.x[s * XP + lane + 32] = __float2half(vB);
                float mks = __shfl_sync(0xffffffffu, mk, rb * 8 + r);
                qA = fmaf(vA, mks, qA);
                qB = fmaf(vB, mks, qB);
            }
        }
        sm.pbuf[w * 64 + lane]      = qA;
        sm.pbuf[w * 64 + lane + 32] = qB;
    }
    __syncthreads();  // S1: x, weights, mask, qin partials ready

    // ---- qin -> q -> a[j][h] ----
    if (tid < 64) {
        float acc = 0.f;
#pragma unroll
        for (int i = 0; i < 16; i++) acc += sm.pbuf[i * 64 + tid];
        float d = 0.f;
#pragma unroll
        for (int i = 0; i < 16; i++) d += sm.red[i];
        sm.qin[tid] = acc / fmaxf(d, 1.0f);
    }
    __syncthreads();  // S2
    if (tid < 64) {
        float acc = 0.f;
#pragma unroll
        for (int j = 0; j < 64; j++) acc = fmaf(sm.qin[j], __ldg(&wq[j * 64 + tid]), acc);
        sm.qsm[tid] = acc;
    }
    __syncthreads();  // S3
    {
        int j = tid >> 3, h = tid & 7;
        float acc = 0.f;
#pragma unroll
        for (int c = 0; c < 8; c++)
            acc = fmaf(sm.qsm[h * 8 + c], __ldg(&wk[j * 64 + h * 8 + c]), acc);
        sm.amt[j * 8 + h] = acc * 0.35355339059327373f;  // 1/sqrt(C)
    }
    __syncthreads();  // S4

    // ---- Phase 3: logits[h][s] = x[s]·a[h], masked ----
    {
        int s = tid;
        uint4 raw[8];
#pragma unroll
        for (int q = 0; q < 8; q++)
            raw[q] = *reinterpret_cast<const uint4*>(&sm.x[s * XP + q * 8]);
        const __half* xr = reinterpret_cast<const __half*>(raw);
        float acc[8] = {0, 0, 0, 0, 0, 0, 0, 0};
#pragma unroll
        for (int j = 0; j < 64; j++) {
            float xv = __half2float(xr[j]);
            const float4* ap = reinterpret_cast<const float4*>(&sm.amt[j * 8]);
            float4 q0 = ap[0], q1 = ap[1];
            acc[0] = fmaf(xv, q0.x, acc[0]); acc[1] = fmaf(xv, q0.y, acc[1]);
            acc[2] = fmaf(xv, q0.z, acc[2]); acc[3] = fmaf(xv, q0.w, acc[3]);
            acc[4] = fmaf(xv, q1.x, acc[4]); acc[5] = fmaf(xv, q1.y, acc[5]);
            acc[6] = fmaf(xv, q1.z, acc[6]); acc[7] = fmaf(xv, q1.w, acc[7]);
        }
        float mkk = sm.maskS[s];
#pragma unroll
        for (int h = 0; h < 8; h++) sm.LG[h * 512 + s] = (mkk != 0.0f) ? acc[h] : -1e9f;
    }
    __syncthreads();  // S5

    // ---- Phase 4: softmax, warp w<8 owns head w ----
    if (w < 8) {
        float vals[16];
        float lm = -3.4e38f;
#pragma unroll
        for (int k = 0; k < 16; k++) {
            vals[k] = sm.LG[w * 512 + lane + k * 32];
            lm = fmaxf(lm, vals[k]);
        }
#pragma unroll
        for (int o = 16; o; o >>= 1) lm = fmaxf(lm, __shfl_xor_sync(0xffffffffu, lm, o));
        float ls = 0.f;
#pragma unroll
        for (int k = 0; k < 16; k++) {
            vals[k] = __expf(vals[k] - lm);
            ls += vals[k];
        }
#pragma unroll
        for (int o = 16; o; o >>= 1) ls += __shfl_xor_sync(0xffffffffu, ls, o);
        float inv = 1.0f / ls;
#pragma unroll
        for (int k = 0; k < 16; k++) sm.LG[w * 512 + lane + k * 32] = vals[k] * inv;
    }
    __syncthreads();  // S6

    // ---- Pass V: v = x @ wv  (warp: 128 rows x 16 cols), v -> vt fp16 ----
    {
        uint32_t B[2][4][2];
#pragma unroll
        for (int nt = 0; nt < 2; nt++)
#pragma unroll
            for (int kt = 0; kt < 4; kt++) {
                int row = nw * 16 + nt * 8 + (lane >> 2);
                int col = kt * 16 + (lane & 3) * 2;
                B[nt][kt][0] = *reinterpret_cast<const uint32_t*>(&sm.wvg[row * XP + col]);
                B[nt][kt][1] = *reinterpret_cast<const uint32_t*>(&sm.wvg[row * XP + col + 8]);
            }
#pragma unroll 1
        for (int mt = 0; mt < 8; mt++) {
            int s0 = mw * 128 + mt * 16;
            uint32_t A[4][4];
#pragma unroll
            for (int kt = 0; kt < 4; kt++)
                ldmA(A[kt], s2u(&sm.x[(s0 + (lane & 15)) * XP + kt * 16 + ((lane >> 4) << 3)]));
            float acc[2][4] = {{0, 0, 0, 0}, {0, 0, 0, 0}};
#pragma unroll
            for (int kt = 0; kt < 4; kt++)
#pragma unroll
                for (int nt = 0; nt < 2; nt++) mma16816(acc[nt], A[kt], B[nt][kt]);
            int r = s0 + (lane >> 2), c = nw * 16 + (lane & 3) * 2;
#pragma unroll
            for (int nt = 0; nt < 2; nt++) {
                *reinterpret_cast<__half2*>(&sm.vt[r * XP + c + nt * 8]) =
                    __floats2half2_rn(acc[nt][0], acc[nt][1]);
                *reinterpret_cast<__half2*>(&sm.vt[(r + 8) * XP + c + nt * 8]) =
                    __floats2half2_rn(acc[nt][2], acc[nt][3]);
            }
        }
    }
    __syncthreads();  // S7: v ready

    // ---- og[hc] = sum_s attn[hc>>3][s] * v[s][hc] ----
    {
        int hc = tid & 63, ck = tid >> 6;
        const float* ar = &sm.LG[(hc >> 3) * 512 + ck * 64];
        float acc = 0.f;
#pragma unroll 8
        for (int i = 0; i < 64; i++)
            acc = fmaf(ar[i], __half2float(sm.vt[(ck * 64 + i) * XP + hc]), acc);
        sm.pbuf[ck * 64 + hc] = acc;
    }
    __syncthreads();  // S8
    if (tid < 64) {
        float acc = 0.f;
#pragma unroll
        for (int ck = 0; ck < 8; ck++) acc += sm.pbuf[ck * 64 + tid];
        sm.og[tid] = acc;
    }
    __syncthreads();  // S9

    // ---- Pass G: t = og * sigmoid(x @ wg + bg) -> vt (overwrite) ----
    {
        uint32_t B[2][4][2];
#pragma unroll
        for (int nt = 0; nt < 2; nt++)
#pragma unroll
            for (int kt = 0; kt < 4; kt++) {
                int row = 64 + nw * 16 + nt * 8 + (lane >> 2);
                int col = kt * 16 + (lane & 3) * 2;
                B[nt][kt][0] = *reinterpret_cast<const uint32_t*>(&sm.wvg[row * XP + col]);
                B[nt][kt][1] = *reinterpret_cast<const uint32_t*>(&sm.wvg[row * XP + col + 8]);
            }
        int cbase = nw * 16 + (lane & 3) * 2;
        float og0[2], og1[2], bg0[2], bg1[2];
#pragma unroll
        for (int nt = 0; nt < 2; nt++) {
            og0[nt] = sm.og[cbase + nt * 8];
            og1[nt] = sm.og[cbase + nt * 8 + 1];
            bg0[nt] = __ldg(&bg[cbase + nt * 8]);
            bg1[nt] = __ldg(&bg[cbase + nt * 8 + 1]);
        }
#pragma unroll 1
        for (int mt = 0; mt < 8; mt++) {
            int s0 = mw * 128 + mt * 16;
            uint32_t A[4][4];
#pragma unroll
            for (int kt = 0; kt < 4; kt++)
                ldmA(A[kt], s2u(&sm.x[(s0 + (lane & 15)) * XP + kt * 16 + ((lane >> 4) << 3)]));
            float acc[2][4] = {{0, 0, 0, 0}, {0, 0, 0, 0}};
#pragma unroll
            for (int kt = 0; kt < 4; kt++)
#pragma unroll
                for (int nt = 0; nt < 2; nt++) mma16816(acc[nt], A[kt], B[nt][kt]);
            int r = s0 + (lane >> 2);
#pragma unroll
            for (int nt = 0; nt < 2; nt++) {
                float t0 = og0[nt] * sgm(acc[nt][0] + bg0[nt]);
                float t1 = og1[nt] * sgm(acc[nt][1] + bg1[nt]);
                float t2 = og0[nt] * sgm(acc[nt][2] + bg0[nt]);
                float t3 = og1[nt] * sgm(acc[nt][3] + bg1[nt]);
                *reinterpret_cast<__half2*>(&sm.vt[r * XP + cbase + nt * 8]) =
                    __floats2half2_rn(t0, t1);
                *reinterpret_cast<__half2*>(&sm.vt[(r + 8) * XP + cbase + nt * 8]) =
                    __floats2half2_rn(t2, t3);
            }
        }
    }
    __syncthreads();  // S10: t ready

    // ---- Pass O: out = (t @ wo + bo) * mask -> global (direct from D frags) ----
    {
        uint32_t B[2][4][2];
#pragma unroll
        for (int nt = 0; nt < 2; nt++)
#pragma unroll
            for (int kt = 0; kt < 4; kt++) {
                int row = nw * 16 + nt * 8 + (lane >> 2);
                int col = kt * 16 + (lane & 3) * 2;
                B[nt][kt][0] = *reinterpret_cast<const uint32_t*>(&sm.wot[row * XP + col]);
                B[nt][kt][1] = *reinterpret_cast<const uint32_t*>(&sm.wot[row * XP + col + 8]);
            }
        int cbase = nw * 16 + (lane & 3) * 2;
        float bo0[2], bo1[2];
#pragma unroll
        for (int nt = 0; nt < 2; nt++) {
            bo0[nt] = __ldg(&bo[cbase + nt * 8]);
            bo1[nt] = __ldg(&bo[cbase + nt * 8 + 1]);
        }
#pragma unroll 1
        for (int mt = 0; mt < 8; mt++) {
            int s0 = mw * 128 + mt * 16;
            uint32_t A[4][4];
#pragma unroll
            for (int kt = 0; kt < 4; kt++)
                ldmA(A[kt], s2u(&sm.vt[(s0 + (lane & 15)) * XP + kt * 16 + ((lane >> 4) << 3)]));
            float acc[2][4] = {{0, 0, 0, 0}, {0, 0, 0, 0}};
#pragma unroll
            for (int kt = 0; kt < 4; kt++)
#pragma unroll
                for (int nt = 0; nt < 2; nt++) mma16816(acc[nt], A[kt], B[nt][kt]);
            int r = s0 + (lane >> 2);
            float mkA = sm.maskS[r], mkB = sm.maskS[r + 8];
#pragma unroll
            for (int nt = 0; nt < 2; nt++) {
                *reinterpret_cast<float2*>(oBase + (size_t)r * rowStride + cbase + nt * 8) =
                    make_float2((acc[nt][0] + bo0[nt]) * mkA, (acc[nt][1] + bo1[nt]) * mkA);
                *reinterpret_cast<float2*>(oBase + (size_t)(r + 8) * rowStride + cbase + nt * 8) =
                    make_float2((acc[nt][2] + bo0[nt]) * mkB, (acc[nt][3] + bo1[nt]) * mkB);
            }
        }
    }
}

extern "C" void kernel_launch(void* const* d_in, const int* in_sizes, int n_in,
                              void* d_out, int out_size)
{
    (void)in_sizes; (void)n_in; (void)out_size;
    const float* m    = (const float*)d_in[0];
    const float* mask = (const float*)d_in[1];
    const float* lnw  = (const float*)d_in[2];
    const float* lnb  = (const float*)d_in[3];
    const float* wq   = (const float*)d_in[4];
    const float* wk   = (const float*)d_in[5];
    const float* wv   = (const float*)d_in[6];
    const float* wg   = (const float*)d_in[7];
    const float* bg   = (const float*)d_in[8];
    const float* wo   = (const float*)d_in[9];
    const float* bo   = (const float*)d_in[10];
    float* out = (float*)d_out;

    cudaFuncSetAttribute(msa_col_global_attn,
                         cudaFuncAttributeMaxDynamicSharedMemorySize,
                         (int)sizeof(SMem));
    msa_col_global_attn<<<Bb * Ll, NT, sizeof(SMem)>>>(
        m, mask, lnw, lnb, wq, wk, wv, wg, bg, wo, bo, out);
}